// round 13
// baseline (speedup 1.0000x reference)
#include <cuda_runtime.h>
#include <math.h>

// Problem constants
#define TT 2048
#define BB 4
#define II 1024
#define HH 1024
#define GG (4 * HH)  // 4096 gate rows

// ---------------- scratch (static device globals; no allocations) ----------
__device__ float g_pre[(size_t)TT * BB * GG];  // [8192][4096] x@W_in^T (128 MB)
__device__ float g_h[2][BB * HH];              // double-buffered hidden state
__device__ unsigned g_bar;                     // single barrier counter (proven)

// packed fp32x2 FMA: d.lo += a.lo*b.lo ; d.hi += a.hi*b.hi (sm_100+)
__device__ __forceinline__ void ffma2(unsigned long long& d, unsigned long long a,
                                      unsigned long long b) {
    asm("fma.rn.f32x2 %0, %1, %2, %0;" : "+l"(d) : "l"(a), "l"(b));
}
__device__ __forceinline__ float ull_lo(unsigned long long v) {
    return __uint_as_float((unsigned)v);
}
__device__ __forceinline__ float ull_hi(unsigned long long v) {
    return __uint_as_float((unsigned)(v >> 32));
}
__device__ __forceinline__ float tanh_fast(float x) {
    float r;
    asm("tanh.approx.f32 %0, %1;" : "=f"(r) : "f"(x));
    return r;
}
// sigma(x) = 0.5*tanh(x/2) + 0.5  (1 MUFU + 2 FMA vs exp+add+rcp chain)
__device__ __forceinline__ float sig_fast(float x) {
    return fmaf(tanh_fast(0.5f * x), 0.5f, 0.5f);
}

// ---------------- kernel 1: pre = x @ W_in^T  (M=8192, N=4096, K=1024) ------
// fp32x2-packed tiled GEMM: BM=128, BN=128, BK=16, 256 threads, 8x8
// tile/thread. Block (0,0) also resets the recurrence scratch.
#define GBM 128
#define GBN 128
#define GBK 16

__global__ __launch_bounds__(256) void gemm_pre(const float* __restrict__ x,
                                                const float* __restrict__ Win) {
    __shared__ __align__(16) float As[GBK][GBM];
    __shared__ __align__(16) float Bs[GBK][GBN];
    const int tid = threadIdx.x;
    const int tx = tid & 15;        // 0..15  -> N (8 cols each)
    const int ty = tid >> 4;        // 0..15  -> M (8 rows each)
    const int mBase = blockIdx.y * GBM;
    const int nBase = blockIdx.x * GBN;

    // ---- inlined init (one block only): reset barrier + h0 = 0 ----
    if (blockIdx.x == 0 && blockIdx.y == 0) {
        if (tid == 0) g_bar = 0u;
#pragma unroll
        for (int i = 0; i < (2 * BB * HH) / 256; i++)
            ((float*)g_h)[i * 256 + tid] = 0.0f;
    }

    unsigned long long acc2[4][8];
#pragma unroll
    for (int i = 0; i < 4; i++)
#pragma unroll
        for (int j = 0; j < 8; j++) acc2[i][j] = 0ull;

    for (int k0 = 0; k0 < II; k0 += GBK) {
#pragma unroll
        for (int q = 0; q < 2; q++) {
            int id = tid * 2 + q;               // 0..511
            int m = id >> 2;
            int k4 = (id & 3) * 4;
            float4 v = *(const float4*)&x[(size_t)(mBase + m) * II + k0 + k4];
            As[k4 + 0][m] = v.x;
            As[k4 + 1][m] = v.y;
            As[k4 + 2][m] = v.z;
            As[k4 + 3][m] = v.w;
        }
#pragma unroll
        for (int q = 0; q < 2; q++) {
            int id = tid * 2 + q;               // 0..511
            int n = id >> 2;
            int k4 = (id & 3) * 4;
            float4 v = *(const float4*)&Win[(size_t)(nBase + n) * II + k0 + k4];
            Bs[k4 + 0][n] = v.x;
            Bs[k4 + 1][n] = v.y;
            Bs[k4 + 2][n] = v.z;
            Bs[k4 + 3][n] = v.w;
        }
        __syncthreads();

#pragma unroll
        for (int kk = 0; kk < GBK; kk++) {
            ulonglong2 t0 = *(const ulonglong2*)&As[kk][ty * 8];
            ulonglong2 t1 = *(const ulonglong2*)&As[kk][ty * 8 + 4];
            unsigned long long a2[4] = {t0.x, t0.y, t1.x, t1.y};
            float bq[8];
            *(float4*)&bq[0] = *(const float4*)&Bs[kk][tx * 8];
            *(float4*)&bq[4] = *(const float4*)&Bs[kk][tx * 8 + 4];
            unsigned long long bd[8];
#pragma unroll
            for (int j = 0; j < 8; j++) {
                unsigned bu = __float_as_uint(bq[j]);
                asm("mov.b64 %0, {%1, %1};" : "=l"(bd[j]) : "r"(bu));
            }
#pragma unroll
            for (int i = 0; i < 4; i++)
#pragma unroll
                for (int j = 0; j < 8; j++) ffma2(acc2[i][j], a2[i], bd[j]);
        }
        __syncthreads();
    }

#pragma unroll
    for (int i = 0; i < 4; i++) {
#pragma unroll
        for (int half = 0; half < 2; half++) {
            float4 vlo = make_float4(ull_lo(acc2[i][half * 4 + 0]), ull_lo(acc2[i][half * 4 + 1]),
                                     ull_lo(acc2[i][half * 4 + 2]), ull_lo(acc2[i][half * 4 + 3]));
            float4 vhi = make_float4(ull_hi(acc2[i][half * 4 + 0]), ull_hi(acc2[i][half * 4 + 1]),
                                     ull_hi(acc2[i][half * 4 + 2]), ull_hi(acc2[i][half * 4 + 3]));
            *(float4*)&g_pre[(size_t)(mBase + ty * 8 + 2 * i + 0) * GG + nBase + tx * 8 + half * 4] = vlo;
            *(float4*)&g_pre[(size_t)(mBase + ty * 8 + 2 * i + 1) * GG + nBase + tx * 8 + half * 4] = vhi;
        }
    }
}

// ---------------- kernel 2: persistent recurrence ---------------------------
// 128 CTAs x 512 threads (16 warps; 1 CTA/SM via 130 KB smem). CTA owns 8
// hidden units (32 gate rows, 128 KB smem, XOR-swizzled). Warp w: gate = w>>2,
// K-quarter = w&3. NEW lane layout: lane = b*8 + k8 (batch in bits 3-4,
// K-chunk in bits 0-2); each lane owns batch b x 32 contiguous K-floats.
// GEMV: 8 rows x 32 K per lane (64 swizzled LDS.128, conflict-free; 128
// FFMA2). Cross-lane reduce is now over only 8 lanes (3 shfl stages, ~28
// instr vs 124). Warp-0 cell update sums 4 K-quarter partials; c-state in
// registers; fast tanh/sigmoid. Grid sync = single-counter atomic barrier.
#define NBLK 128
#define UPB 8
#define ROWS 32
#define RTH 512

__global__ __launch_bounds__(RTH) void lstm_rec(const float* __restrict__ Whh,
                                                float* __restrict__ out) {
    extern __shared__ float sm[];
    float* W_s = sm;                          // [32][1024] 128 KB (swizzled rows)
    float* part_s = W_s + ROWS * HH;          // [4 quarter][4 gate][32]  2 KB

    const int tid = threadIdx.x;
    const int blk = blockIdx.x;
    const int warp = tid >> 5;
    const int lane = tid & 31;
    const int gate = warp >> 2;               // 0..3
    const int q = warp & 3;                   // K-quarter 0..3
    const int b = lane >> 3;                  // batch 0..3
    const int k8 = lane & 7;                  // K-chunk-of-32 within quarter

    // Stage W with per-row XOR swizzle: 16B chunk c4 (0..255) of local row r
    // is stored at chunk c4 ^ ((c4>>3)&7). Load side XORs the same pattern ->
    // conflict-free 128B-strided reads. Local row r = gate*8 + u.
    for (int id = tid; id < ROWS * (HH / 4); id += RTH) {
        int r = id / (HH / 4);
        int c4 = id % (HH / 4);
        int g = r >> 3, ul = r & 7;
        int c4s = c4 ^ ((c4 >> 3) & 7);
        ((float4*)&W_s[r * HH])[c4s] =
            ((const float4*)&Whh[(size_t)(g * HH + blk * UPB + ul) * HH])[c4];
    }
    __syncthreads();

    // warp0 persistent cell state: lane = u*4 + bw
    const int u = lane >> 2, bw = lane & 3;
    const int ug = blk * UPB + u;
    float c_val = 0.0f;

    // 8 precomputed lane pointers into the swizzled W quarter: chunk position
    // for (k8, i) is q*64 + k8*8 + (i^k8)  ->  byte = q*1024 + k8*128 + (i^k8)*16.
    // Row j then adds an immediate j*HH*4 = j*4096 bytes.
    const char* wq = (const char*)(W_s + gate * UPB * HH) + q * 1024 + k8 * 128;
    const char* wp[8];
#pragma unroll
    for (int i = 0; i < 8; i++) wp[i] = wq + ((i * 16) ^ (k8 * 16));

    for (int t = 0; t < TT; t++) {
        // Prefetch this step's pre-activations (consumed ~1500 cyc later).
        float pre_r[4];
        if (warp == 0) {
#pragma unroll
            for (int g = 0; g < 4; g++)
                pre_r[g] = __ldcs(&g_pre[(size_t)(t * BB + bw) * GG + g * HH + ug]);
        }

        // h: L2 -> registers. Lane's slice = batch b, 32 contiguous floats.
        const float* hb = g_h[t & 1] + b * HH + q * 256 + k8 * 32;
        ulonglong2 hv[8];
#pragma unroll
        for (int i = 0; i < 8; i++)
            hv[i] = __ldcg((const ulonglong2*)(hb + i * 4));

        // GEMV: 8 rows x 32 K per lane. acc[j] packs (k, k+1) pairs.
        unsigned long long acc[8];
#pragma unroll
        for (int j = 0; j < 8; j++) acc[j] = 0ull;
#pragma unroll
        for (int j = 0; j < 8; j++) {
#pragma unroll
            for (int i = 0; i < 8; i++) {
                ulonglong2 wv = *(const ulonglong2*)(wp[i] + j * (HH * 4));
                ffma2(acc[j], wv.x, hv[i].x);
                ffma2(acc[j], wv.y, hv[i].y);
            }
        }

        // Collapse packed halves -> 8 scalars (one per row j).
        float a[8];
#pragma unroll
        for (int j = 0; j < 8; j++) a[j] = ull_lo(acc[j]) + ull_hi(acc[j]);

        // Transpose-reduce over the 8 k8-lanes within each batch group:
        // after 3 stages, lane b*8 + j holds the full sum for (row j, batch b).
#pragma unroll
        for (int s = 4; s >= 1; s >>= 1) {
            const bool up = (lane & s) != 0;
#pragma unroll
            for (int k = 0; k < s; k++) {
                float sendv = up ? a[k] : a[k + s];
                float keepv = up ? a[k + s] : a[k];
                float got = __shfl_xor_sync(0xFFFFFFFFu, sendv, s);
                a[k] = keepv + got;
            }
        }
        part_s[(q * 4 + gate) * 32 + k8 * 4 + b] = a[0];  // index j*4 + b
        __syncthreads();

        // Cell update: warp 0, lane = u*4 + bw. Sum the 4 K-quarter partials.
        if (tid < 32) {
            float gsum[4];
#pragma unroll
            for (int g = 0; g < 4; g++) {
                gsum[g] = pre_r[g];
#pragma unroll
                for (int qq = 0; qq < 4; qq++)
                    gsum[g] += part_s[(qq * 4 + g) * 32 + lane];
            }
            float i_s = sig_fast(gsum[0]);
            float f_s = sig_fast(gsum[1]);
            float g_t = tanh_fast(gsum[2]);
            float o_s = sig_fast(gsum[3]);
            c_val = f_s * c_val + i_s * g_t;
            float h = o_s * tanh_fast(c_val);
            g_h[(t + 1) & 1][bw * HH + ug] = h;                     // next step input
            out[(size_t)(t * BB + bw) * HH + ug] = h;               // layer output
            if (t == TT - 1) {
                out[(size_t)TT * BB * HH + bw * HH + ug] = h;           // h_T
                out[(size_t)TT * BB * HH + BB * HH + bw * HH + ug] = c_val;  // c_T
            }
            __syncwarp();
            if (lane == 0) {
                __threadfence();  // cumulative: orders warp-0's h stores (via syncwarp)
                atomicAdd(&g_bar, 1u);
                const unsigned target = (unsigned)(t + 1) * NBLK;
                while (*((volatile unsigned*)&g_bar) < target) {
                }
            }
        }
        __syncthreads();
    }
}

// ---------------- launch ----------------------------------------------------
extern "C" void kernel_launch(void* const* d_in, const int* in_sizes, int n_in,
                              void* d_out, int out_size) {
    const float* x   = (const float*)d_in[0];   // [T,B,I]
    const float* Win = (const float*)d_in[1];   // [4H,I]
    const float* Whh = (const float*)d_in[2];   // [4H,H]
    float* out = (float*)d_out;

    const int smem_bytes = (ROWS * HH + 4 * 4 * 32) * (int)sizeof(float);
    cudaFuncSetAttribute(lstm_rec, cudaFuncAttributeMaxDynamicSharedMemorySize, smem_bytes);

    gemm_pre<<<dim3(GG / GBN, (TT * BB) / GBM), 256>>>(x, Win);
    lstm_rec<<<NBLK, RTH, smem_bytes>>>(Whh, out);
}

// round 14
// speedup vs baseline: 1.5040x; 1.5040x over previous
#include <cuda_runtime.h>
#include <math.h>

// Problem constants
#define TT 2048
#define BB 4
#define II 1024
#define HH 1024
#define GG (4 * HH)  // 4096 gate rows

// ---------------- scratch (static device globals; no allocations) ----------
__device__ float g_pre[(size_t)TT * BB * GG];  // [8192][4096] x@W_in^T (128 MB)
__device__ float g_h[2][BB * HH];              // double-buffered hidden state
__device__ unsigned g_bar;                     // single barrier counter (proven)

// packed fp32x2 FMA: d.lo += a.lo*b.lo ; d.hi += a.hi*b.hi (sm_100+)
__device__ __forceinline__ void ffma2(unsigned long long& d, unsigned long long a,
                                      unsigned long long b) {
    asm("fma.rn.f32x2 %0, %1, %2, %0;" : "+l"(d) : "l"(a), "l"(b));
}
__device__ __forceinline__ float ull_lo(unsigned long long v) {
    return __uint_as_float((unsigned)v);
}
__device__ __forceinline__ float ull_hi(unsigned long long v) {
    return __uint_as_float((unsigned)(v >> 32));
}
__device__ __forceinline__ float tanh_fast(float x) {
    float r;
    asm("tanh.approx.f32 %0, %1;" : "=f"(r) : "f"(x));
    return r;
}
// sigma(x) = 0.5*tanh(x/2) + 0.5  (1 MUFU + 2 FMA vs exp+add+rcp chain)
__device__ __forceinline__ float sig_fast(float x) {
    return fmaf(tanh_fast(0.5f * x), 0.5f, 0.5f);
}

// ---------------- kernel 1: pre = x @ W_in^T  (M=8192, N=4096, K=1024) ------
// fp32x2-packed tiled GEMM: BM=128, BN=128, BK=16, 256 threads, 8x8
// tile/thread. Block (0,0) also resets the recurrence scratch.
#define GBM 128
#define GBN 128
#define GBK 16

__global__ __launch_bounds__(256) void gemm_pre(const float* __restrict__ x,
                                                const float* __restrict__ Win) {
    __shared__ __align__(16) float As[GBK][GBM];
    __shared__ __align__(16) float Bs[GBK][GBN];
    const int tid = threadIdx.x;
    const int tx = tid & 15;        // 0..15  -> N (8 cols each)
    const int ty = tid >> 4;        // 0..15  -> M (8 rows each)
    const int mBase = blockIdx.y * GBM;
    const int nBase = blockIdx.x * GBN;

    // ---- inlined init (one block only): reset barrier + h0 = 0 ----
    if (blockIdx.x == 0 && blockIdx.y == 0) {
        if (tid == 0) g_bar = 0u;
#pragma unroll
        for (int i = 0; i < (2 * BB * HH) / 256; i++)
            ((float*)g_h)[i * 256 + tid] = 0.0f;
    }

    unsigned long long acc2[4][8];
#pragma unroll
    for (int i = 0; i < 4; i++)
#pragma unroll
        for (int j = 0; j < 8; j++) acc2[i][j] = 0ull;

    for (int k0 = 0; k0 < II; k0 += GBK) {
#pragma unroll
        for (int q = 0; q < 2; q++) {
            int id = tid * 2 + q;               // 0..511
            int m = id >> 2;
            int k4 = (id & 3) * 4;
            float4 v = *(const float4*)&x[(size_t)(mBase + m) * II + k0 + k4];
            As[k4 + 0][m] = v.x;
            As[k4 + 1][m] = v.y;
            As[k4 + 2][m] = v.z;
            As[k4 + 3][m] = v.w;
        }
#pragma unroll
        for (int q = 0; q < 2; q++) {
            int id = tid * 2 + q;               // 0..511
            int n = id >> 2;
            int k4 = (id & 3) * 4;
            float4 v = *(const float4*)&Win[(size_t)(nBase + n) * II + k0 + k4];
            Bs[k4 + 0][n] = v.x;
            Bs[k4 + 1][n] = v.y;
            Bs[k4 + 2][n] = v.z;
            Bs[k4 + 3][n] = v.w;
        }
        __syncthreads();

#pragma unroll
        for (int kk = 0; kk < GBK; kk++) {
            ulonglong2 t0 = *(const ulonglong2*)&As[kk][ty * 8];
            ulonglong2 t1 = *(const ulonglong2*)&As[kk][ty * 8 + 4];
            unsigned long long a2[4] = {t0.x, t0.y, t1.x, t1.y};
            float bq[8];
            *(float4*)&bq[0] = *(const float4*)&Bs[kk][tx * 8];
            *(float4*)&bq[4] = *(const float4*)&Bs[kk][tx * 8 + 4];
            unsigned long long bd[8];
#pragma unroll
            for (int j = 0; j < 8; j++) {
                unsigned bu = __float_as_uint(bq[j]);
                asm("mov.b64 %0, {%1, %1};" : "=l"(bd[j]) : "r"(bu));
            }
#pragma unroll
            for (int i = 0; i < 4; i++)
#pragma unroll
                for (int j = 0; j < 8; j++) ffma2(acc2[i][j], a2[i], bd[j]);
        }
        __syncthreads();
    }

#pragma unroll
    for (int i = 0; i < 4; i++) {
#pragma unroll
        for (int half = 0; half < 2; half++) {
            float4 vlo = make_float4(ull_lo(acc2[i][half * 4 + 0]), ull_lo(acc2[i][half * 4 + 1]),
                                     ull_lo(acc2[i][half * 4 + 2]), ull_lo(acc2[i][half * 4 + 3]));
            float4 vhi = make_float4(ull_hi(acc2[i][half * 4 + 0]), ull_hi(acc2[i][half * 4 + 1]),
                                     ull_hi(acc2[i][half * 4 + 2]), ull_hi(acc2[i][half * 4 + 3]));
            *(float4*)&g_pre[(size_t)(mBase + ty * 8 + 2 * i + 0) * GG + nBase + tx * 8 + half * 4] = vlo;
            *(float4*)&g_pre[(size_t)(mBase + ty * 8 + 2 * i + 1) * GG + nBase + tx * 8 + half * 4] = vhi;
        }
    }
}

// ---------------- kernel 2: persistent recurrence ---------------------------
// 128 CTAs x 512 threads (16 warps; 1 CTA/SM via 146 KB smem). CTA owns 8
// hidden units (32 gate rows, 128 KB smem, XOR-swizzled rows). Warp w:
// gate = w>>2, K-quarter = w&3. Lane = b*8 + k8: batch b x 32 contiguous K.
// h is staged into smem in a TRANSPOSED layout h4[q*256 + i*32 + lane] so the
// GEMV h-read is a conflict-free LDS.128 at 16B lane stride (fixes R13's
// 32-line LDG wavefront explosion). GEMV: 8 rows x 32 K per lane, 64 swizzled
// W LDS (conflict-free broadcast x4 batches) + 8 h LDS + 128 FFMA2. 3-stage
// 8-lane reduce (proven in R13). Warp-0 cell update; single-counter barrier.
#define NBLK 128
#define UPB 8
#define ROWS 32
#define RTH 512

__global__ __launch_bounds__(RTH) void lstm_rec(const float* __restrict__ Whh,
                                                float* __restrict__ out) {
    extern __shared__ float sm[];
    // [0, 32*1024) floats: W (swizzled). [32K, 36K): h transposed. then part_s.
    const ulonglong2* W2 = (const ulonglong2*)sm;            // 32*256 chunks
    float4* h4w = (float4*)(sm + ROWS * HH);                 // 1024 chunks (write view)
    const ulonglong2* h2 = (const ulonglong2*)(sm + ROWS * HH);  // read view
    float* part_s = sm + ROWS * HH + BB * HH;                // 512 floats

    const int tid = threadIdx.x;
    const int blk = blockIdx.x;
    const int warp = tid >> 5;
    const int lane = tid & 31;
    const int gate = warp >> 2;               // 0..3
    const int q = warp & 3;                   // K-quarter 0..3
    const int b = lane >> 3;                  // batch 0..3
    const int k8 = lane & 7;                  // K-chunk-of-32 within quarter

    // Stage W with per-row XOR swizzle (R13-proven): chunk c4 stored at
    // c4 ^ ((c4>>3)&7). Local row r = gate*8 + unit.
    {
        float4* W4w = (float4*)sm;
        for (int id = tid; id < ROWS * (HH / 4); id += RTH) {
            int r = id / (HH / 4);
            int c4 = id % (HH / 4);
            int g = r >> 3, ul = r & 7;
            int c4s = c4 ^ ((c4 >> 3) & 7);
            W4w[r * 256 + c4s] =
                ((const float4*)&Whh[(size_t)(g * HH + blk * UPB + ul) * HH])[c4];
        }
    }
    __syncthreads();

    // warp0 persistent cell state: lane = u*4 + bw
    const int u = lane >> 2, bw = lane & 3;
    const int ug = blk * UPB + u;
    float c_val = 0.0f;

    // Per-lane W chunk indices (swizzled): for (row j, i) the chunk is
    // j*256 + q*64 + k8*8 + (i ^ k8), plus gate row base.
    const int wrow0 = gate * UPB * 256;
    int wci[8];
#pragma unroll
    for (int i = 0; i < 8; i++) wci[i] = q * 64 + k8 * 8 + (i ^ k8);
    const int hbase = q * 256 + lane;  // + i*32 per chunk

    for (int t = 0; t < TT; t++) {
        // Prefetch this step's pre-activations (consumed ~1500 cyc later).
        float pre_r[4];
        if (warp == 0) {
#pragma unroll
            for (int g = 0; g < 4; g++)
                pre_r[g] = __ldcs(&g_pre[(size_t)(t * BB + bw) * GG + g * HH + ug]);
        }

        // Stage h transposed: global float4 f = b*256 + q*64 + k8*8 + i goes
        // to smem chunk q*256 + i*32 + b*8 + k8. LDG coalesced; STS scatter.
        {
            const float4* hg4 = (const float4*)g_h[t & 1];
#pragma unroll
            for (int rep = 0; rep < 2; rep++) {
                int f = tid + rep * RTH;       // 0..1023
                int bb = f >> 8;
                int rem = f & 255;
                int qq = rem >> 6, kk = (rem >> 3) & 7, ii = rem & 7;
                h4w[qq * 256 + ii * 32 + bb * 8 + kk] = __ldcg(&hg4[f]);
            }
        }
        __syncthreads();

        // GEMV: 8 rows x 32 K per lane. acc[j] packs (k, k+1) pairs.
        unsigned long long acc[8];
#pragma unroll
        for (int j = 0; j < 8; j++) acc[j] = 0ull;
#pragma unroll
        for (int i = 0; i < 8; i++) {
            ulonglong2 hv = h2[hbase + i * 32];
#pragma unroll
            for (int j = 0; j < 8; j++) {
                ulonglong2 wv = W2[wrow0 + j * 256 + wci[i]];
                ffma2(acc[j], wv.x, hv.x);
                ffma2(acc[j], wv.y, hv.y);
            }
        }

        // Collapse packed halves -> 8 scalars (one per row j).
        float a[8];
#pragma unroll
        for (int j = 0; j < 8; j++) a[j] = ull_lo(acc[j]) + ull_hi(acc[j]);

        // 3-stage transpose-reduce over the 8 k8-lanes of each batch group:
        // lane b*8 + j ends with the full (row j, batch b) sum. (R13-proven.)
#pragma unroll
        for (int s = 4; s >= 1; s >>= 1) {
            const bool up = (lane & s) != 0;
#pragma unroll
            for (int k = 0; k < s; k++) {
                float sendv = up ? a[k] : a[k + s];
                float keepv = up ? a[k + s] : a[k];
                float got = __shfl_xor_sync(0xFFFFFFFFu, sendv, s);
                a[k] = keepv + got;
            }
        }
        part_s[(q * 4 + gate) * 32 + k8 * 4 + b] = a[0];  // index row*4 + batch
        __syncthreads();

        // Cell update: warp 0, lane = u*4 + bw. Sum the 4 K-quarter partials.
        if (tid < 32) {
            float gsum[4];
#pragma unroll
            for (int g = 0; g < 4; g++) {
                gsum[g] = pre_r[g];
#pragma unroll
                for (int qq = 0; qq < 4; qq++)
                    gsum[g] += part_s[(qq * 4 + g) * 32 + lane];
            }
            float i_s = sig_fast(gsum[0]);
            float f_s = sig_fast(gsum[1]);
            float g_t = tanh_fast(gsum[2]);
            float o_s = sig_fast(gsum[3]);
            c_val = f_s * c_val + i_s * g_t;
            float h = o_s * tanh_fast(c_val);
            g_h[(t + 1) & 1][bw * HH + ug] = h;                     // next step input
            out[(size_t)(t * BB + bw) * HH + ug] = h;               // layer output
            if (t == TT - 1) {
                out[(size_t)TT * BB * HH + bw * HH + ug] = h;           // h_T
                out[(size_t)TT * BB * HH + BB * HH + bw * HH + ug] = c_val;  // c_T
            }
            __syncwarp();
            if (lane == 0) {
                __threadfence();  // cumulative: orders warp-0's h stores (via syncwarp)
                atomicAdd(&g_bar, 1u);
                const unsigned target = (unsigned)(t + 1) * NBLK;
                while (*((volatile unsigned*)&g_bar) < target) {
                }
            }
        }
        __syncthreads();
    }
}

// ---------------- launch ----------------------------------------------------
extern "C" void kernel_launch(void* const* d_in, const int* in_sizes, int n_in,
                              void* d_out, int out_size) {
    const float* x   = (const float*)d_in[0];   // [T,B,I]
    const float* Win = (const float*)d_in[1];   // [4H,I]
    const float* Whh = (const float*)d_in[2];   // [4H,H]
    float* out = (float*)d_out;

    const int smem_bytes = (ROWS * HH + BB * HH + 4 * 4 * 32) * (int)sizeof(float);
    cudaFuncSetAttribute(lstm_rec, cudaFuncAttributeMaxDynamicSharedMemorySize, smem_bytes);

    gemm_pre<<<dim3(GG / GBN, (TT * BB) / GBM), 256>>>(x, Win);
    lstm_rec<<<NBLK, RTH, smem_bytes>>>(Whh, out);
}

// round 15
// speedup vs baseline: 2.1112x; 1.4037x over previous
#include <cuda_runtime.h>
#include <math.h>

// Problem constants
#define TT 2048
#define BB 4
#define II 1024
#define HH 1024
#define GG (4 * HH)  // 4096 gate rows

// ---------------- scratch (static device globals; no allocations) ----------
__device__ float g_pre[(size_t)TT * BB * GG];  // [8192][4096] x@W_in^T (128 MB)
__device__ float g_h[2][BB * HH];              // double-buffered hidden state
__device__ unsigned g_bar;                     // single barrier counter (proven)

// packed fp32x2 FMA: d.lo += a.lo*b.lo ; d.hi += a.hi*b.hi (sm_100+)
__device__ __forceinline__ void ffma2(unsigned long long& d, unsigned long long a,
                                      unsigned long long b) {
    asm("fma.rn.f32x2 %0, %1, %2, %0;" : "+l"(d) : "l"(a), "l"(b));
}
__device__ __forceinline__ float ull_lo(unsigned long long v) {
    return __uint_as_float((unsigned)v);
}
__device__ __forceinline__ float ull_hi(unsigned long long v) {
    return __uint_as_float((unsigned)(v >> 32));
}
__device__ __forceinline__ float tanh_fast(float x) {
    float r;
    asm("tanh.approx.f32 %0, %1;" : "=f"(r) : "f"(x));
    return r;
}
// sigma(x) = 0.5*tanh(x/2) + 0.5  (1 MUFU + 2 FMA vs exp+add+rcp chain)
__device__ __forceinline__ float sig_fast(float x) {
    return fmaf(tanh_fast(0.5f * x), 0.5f, 0.5f);
}

// ---------------- kernel 1: pre = x @ W_in^T  (M=8192, N=4096, K=1024) ------
// fp32x2-packed tiled GEMM: BM=128, BN=128, BK=16, 256 threads, 8x8
// tile/thread. Block (0,0) also resets the recurrence scratch.
#define GBM 128
#define GBN 128
#define GBK 16

__global__ __launch_bounds__(256) void gemm_pre(const float* __restrict__ x,
                                                const float* __restrict__ Win) {
    __shared__ __align__(16) float As[GBK][GBM];
    __shared__ __align__(16) float Bs[GBK][GBN];
    const int tid = threadIdx.x;
    const int tx = tid & 15;        // 0..15  -> N (8 cols each)
    const int ty = tid >> 4;        // 0..15  -> M (8 rows each)
    const int mBase = blockIdx.y * GBM;
    const int nBase = blockIdx.x * GBN;

    // ---- inlined init (one block only): reset barrier + h0 = 0 ----
    if (blockIdx.x == 0 && blockIdx.y == 0) {
        if (tid == 0) g_bar = 0u;
#pragma unroll
        for (int i = 0; i < (2 * BB * HH) / 256; i++)
            ((float*)g_h)[i * 256 + tid] = 0.0f;
    }

    unsigned long long acc2[4][8];
#pragma unroll
    for (int i = 0; i < 4; i++)
#pragma unroll
        for (int j = 0; j < 8; j++) acc2[i][j] = 0ull;

    for (int k0 = 0; k0 < II; k0 += GBK) {
#pragma unroll
        for (int q = 0; q < 2; q++) {
            int id = tid * 2 + q;               // 0..511
            int m = id >> 2;
            int k4 = (id & 3) * 4;
            float4 v = *(const float4*)&x[(size_t)(mBase + m) * II + k0 + k4];
            As[k4 + 0][m] = v.x;
            As[k4 + 1][m] = v.y;
            As[k4 + 2][m] = v.z;
            As[k4 + 3][m] = v.w;
        }
#pragma unroll
        for (int q = 0; q < 2; q++) {
            int id = tid * 2 + q;               // 0..511
            int n = id >> 2;
            int k4 = (id & 3) * 4;
            float4 v = *(const float4*)&Win[(size_t)(nBase + n) * II + k0 + k4];
            Bs[k4 + 0][n] = v.x;
            Bs[k4 + 1][n] = v.y;
            Bs[k4 + 2][n] = v.z;
            Bs[k4 + 3][n] = v.w;
        }
        __syncthreads();

#pragma unroll
        for (int kk = 0; kk < GBK; kk++) {
            ulonglong2 t0 = *(const ulonglong2*)&As[kk][ty * 8];
            ulonglong2 t1 = *(const ulonglong2*)&As[kk][ty * 8 + 4];
            unsigned long long a2[4] = {t0.x, t0.y, t1.x, t1.y};
            float bq[8];
            *(float4*)&bq[0] = *(const float4*)&Bs[kk][tx * 8];
            *(float4*)&bq[4] = *(const float4*)&Bs[kk][tx * 8 + 4];
            unsigned long long bd[8];
#pragma unroll
            for (int j = 0; j < 8; j++) {
                unsigned bu = __float_as_uint(bq[j]);
                asm("mov.b64 %0, {%1, %1};" : "=l"(bd[j]) : "r"(bu));
            }
#pragma unroll
            for (int i = 0; i < 4; i++)
#pragma unroll
                for (int j = 0; j < 8; j++) ffma2(acc2[i][j], a2[i], bd[j]);
        }
        __syncthreads();
    }

#pragma unroll
    for (int i = 0; i < 4; i++) {
#pragma unroll
        for (int half = 0; half < 2; half++) {
            float4 vlo = make_float4(ull_lo(acc2[i][half * 4 + 0]), ull_lo(acc2[i][half * 4 + 1]),
                                     ull_lo(acc2[i][half * 4 + 2]), ull_lo(acc2[i][half * 4 + 3]));
            float4 vhi = make_float4(ull_hi(acc2[i][half * 4 + 0]), ull_hi(acc2[i][half * 4 + 1]),
                                     ull_hi(acc2[i][half * 4 + 2]), ull_hi(acc2[i][half * 4 + 3]));
            *(float4*)&g_pre[(size_t)(mBase + ty * 8 + 2 * i + 0) * GG + nBase + tx * 8 + half * 4] = vlo;
            *(float4*)&g_pre[(size_t)(mBase + ty * 8 + 2 * i + 1) * GG + nBase + tx * 8 + half * 4] = vhi;
        }
    }
}

// ---------------- kernel 2: persistent recurrence ---------------------------
// R12 structure (proven 8.21 ms) + split barrier. 128 CTAs x 512 threads
// (16 warps; 1 CTA/SM via 130 KB smem). CTA owns 8 hidden units (32 gate rows,
// 128 KB smem). Warp w: gate = w>>2, K-quarter = w&3; 8 rows x 4 batches over
// K=256, packed FFMA2, h loaded L2->registers (lane-private slices), 5-stage
// shfl transpose-reduce. Tail: warps 1-15 bar.arrive(1) then spin on a smem
// flag; warp 0 bar.sync(1), cell update, fence+atomic+poll, then releases via
// the flag (replaces the release __syncthreads).
#define NBLK 128
#define UPB 8
#define ROWS 32
#define RTH 512

__global__ __launch_bounds__(RTH) void lstm_rec(const float* __restrict__ Whh,
                                                float* __restrict__ out) {
    extern __shared__ float sm[];
    float* W_s = sm;                          // [32][1024] 128 KB
    float* part_s = W_s + ROWS * HH;          // [4 quarter][4 gate][32]  2 KB
    volatile unsigned* sflag = (volatile unsigned*)(part_s + 4 * 4 * 32);

    const int tid = threadIdx.x;
    const int blk = blockIdx.x;
    const int warp = tid >> 5;
    const int lane = tid & 31;
    const int gate = warp >> 2;               // 0..3
    const int q = warp & 3;                   // K-quarter 0..3

    // Stage W: local row r = gate*8 + u  <-  Whh[gate*1024 + blk*8 + u]
    for (int id = tid; id < ROWS * (HH / 4); id += RTH) {
        int r = id / (HH / 4);
        int c4 = id % (HH / 4);
        int g = r >> 3, ul = r & 7;
        ((float4*)&W_s[r * HH])[c4] =
            ((const float4*)&Whh[(size_t)(g * HH + blk * UPB + ul) * HH])[c4];
    }
    if (tid == 0) *sflag = 0u;
    __syncthreads();

    // warp0 persistent cell state: lane = u*4 + b
    const int u = lane >> 2, b = lane & 3;
    const int ug = blk * UPB + u;
    float c_val = 0.0f;

    const float* Wbase = &W_s[gate * UPB * HH + q * (HH / 4)];
    const int hoff = q * (HH / 4) + lane * 4;  // this lane's K slice base

    for (int t = 0; t < TT; t++) {
        // Prefetch this step's pre-activations (consumed ~1500 cyc later).
        float pre_r[4];
        if (warp == 0) {
#pragma unroll
            for (int g = 0; g < 4; g++)
                pre_r[g] = __ldcs(&g_pre[(size_t)(t * BB + b) * GG + g * HH + ug]);
        }

        // h: L2 -> registers, lane-private slices (issue all 8 LDG.128 up
        // front; latency overlapped by the 16-warp mix and the W LDS stream).
        const float* hg = g_h[t & 1];
        ulonglong2 hv[2][4];
#pragma unroll
        for (int it = 0; it < 2; it++)
#pragma unroll
            for (int bb = 0; bb < 4; bb++)
                hv[it][bb] = __ldcg((const ulonglong2*)&hg[bb * HH + hoff + it * 128]);

        // GEMV: 8 rows x 4 batches over K=256 (2 iterations of 128).
        unsigned long long acc[8][4];
#pragma unroll
        for (int j = 0; j < 8; j++)
#pragma unroll
            for (int bb = 0; bb < 4; bb++) acc[j][bb] = 0ull;

#pragma unroll
        for (int it = 0; it < 2; it++) {
            const int base = it * 128 + lane * 4;
#pragma unroll
            for (int j = 0; j < 8; j++) {
                ulonglong2 wv = *(const ulonglong2*)&Wbase[j * HH + base];
#pragma unroll
                for (int bb = 0; bb < 4; bb++) {
                    ffma2(acc[j][bb], wv.x, hv[it][bb].x);
                    ffma2(acc[j][bb], wv.y, hv[it][bb].y);
                }
            }
        }

        // Collapse packed accumulators -> 32 scalars (index = j*4 + bb = u*4+b)
        float a[32];
#pragma unroll
        for (int j = 0; j < 8; j++)
#pragma unroll
            for (int bb = 0; bb < 4; bb++)
                a[j * 4 + bb] = ull_lo(acc[j][bb]) + ull_hi(acc[j][bb]);

        // Register transpose-reduce: lane l ends with full sum of index l.
#pragma unroll
        for (int s = 16; s >= 1; s >>= 1) {
            const bool up = (lane & s) != 0;
#pragma unroll
            for (int k = 0; k < s; k++) {
                float sendv = up ? a[k] : a[k + s];
                float keepv = up ? a[k + s] : a[k];
                float got = __shfl_xor_sync(0xFFFFFFFFu, sendv, s);
                a[k] = keepv + got;
            }
        }
        part_s[(q * 4 + gate) * 32 + lane] = a[0];

        if (warp == 0) {
            // Wait for all producers' part_s (480 arrivals + 32 sync = 512).
            asm volatile("bar.sync 1, %0;" ::"r"(RTH) : "memory");

            // Cell update: lane = u*4 + b. Sum the 4 K-quarter partials.
            float gsum[4];
#pragma unroll
            for (int g = 0; g < 4; g++) {
                gsum[g] = pre_r[g];
#pragma unroll
                for (int qq = 0; qq < 4; qq++)
                    gsum[g] += part_s[(qq * 4 + g) * 32 + lane];
            }
            float i_s = sig_fast(gsum[0]);
            float f_s = sig_fast(gsum[1]);
            float g_t = tanh_fast(gsum[2]);
            float o_s = sig_fast(gsum[3]);
            c_val = f_s * c_val + i_s * g_t;
            float h = o_s * tanh_fast(c_val);
            g_h[(t + 1) & 1][b * HH + ug] = h;                      // next step input
            out[(size_t)(t * BB + b) * HH + ug] = h;                // layer output
            if (t == TT - 1) {
                out[(size_t)TT * BB * HH + b * HH + ug] = h;            // h_T
                out[(size_t)TT * BB * HH + BB * HH + b * HH + ug] = c_val;  // c_T
            }
            __syncwarp();
            if (lane == 0) {
                __threadfence();  // cumulative: orders warp-0's h stores (via syncwarp)
                atomicAdd(&g_bar, 1u);
                const unsigned target = (unsigned)(t + 1) * NBLK;
                while (*((volatile unsigned*)&g_bar) < target) {
                }
            }
            __syncwarp();         // all warp-0 lanes wait for the poll
            if (lane == 0) *sflag = (unsigned)(t + 1);  // release the CTA
        } else {
            // Producer: signal part_s written, then spin on the smem flag
            // until warp 0 certifies h_{t+1} is globally visible.
            asm volatile("bar.arrive 1, %0;" ::"r"(RTH) : "memory");
            const unsigned tgt = (unsigned)(t + 1);
            while (*sflag < tgt) {
            }
        }
    }
}

// ---------------- launch ----------------------------------------------------
extern "C" void kernel_launch(void* const* d_in, const int* in_sizes, int n_in,
                              void* d_out, int out_size) {
    const float* x   = (const float*)d_in[0];   // [T,B,I]
    const float* Win = (const float*)d_in[1];   // [4H,I]
    const float* Whh = (const float*)d_in[2];   // [4H,H]
    float* out = (float*)d_out;

    const int smem_bytes = (ROWS * HH + 4 * 4 * 32 + 8) * (int)sizeof(float);
    cudaFuncSetAttribute(lstm_rec, cudaFuncAttributeMaxDynamicSharedMemorySize, smem_bytes);

    gemm_pre<<<dim3(GG / GBN, (TT * BB) / GBM), 256>>>(x, Win);
    lstm_rec<<<NBLK, RTH, smem_bytes>>>(Whh, out);
}